// round 6
// baseline (speedup 1.0000x reference)
#include <cuda_runtime.h>
#include <cuda_fp16.h>
#include <cstdint>

// ============================================================================
// IterativeFixedPoint: z_{k+1} = tanh(z_k @ W^T + b + x), 25 fixed iterations.
// Classic tensor-core path (mma.sync + ldmatrix) — the harness compiles for
// plain sm_103 (no 'a' feature target), so tcgen05/TMEM are unavailable.
//
//  - 256 CTAs x 128 rows; 8 warps/CTA, 16 rows/warp. Persistent: z never
//    leaves the SM; rows are warp-private -> NO block sync in the main loop.
//  - W as fp16 in SMEM (128 KB), 512B rows, XOR-swizzled for ldmatrix.
//  - z kept in registers as mma A-fragments (fp16x2). The D-fragment layout
//    maps 1:1 onto the next iteration's A-fragment layout.
//  - x read fp32 from gmem (L2-resident) in the epilogue; b fp32 in SMEM.
//  - iteration 0 skips the GEMM (z0 = 0 -> u = b + x).
// ============================================================================

#define NT       256
#define NB       256
#define ITERS    25
#define SMEM_WOFF 0
#define SMEM_BOFF (256 * 512)            // after W tile (128 KB)
#define SMEM_TOTAL (256 * 512 + 256 * 4) // + 1 KB bias

__device__ __forceinline__ uint32_t smem_u32(const void* p) {
    uint32_t a;
    asm("{ .reg .u64 t; cvta.to.shared.u64 t, %1; cvt.u32.u64 %0, t; }"
        : "=r"(a) : "l"(p));
    return a;
}

// tanh(u) = 1 - 2/(1 + e^{2u}); ex2/rcp approx, ~1e-6 abs err, deterministic.
__device__ __forceinline__ float tanh_fast(float u) {
    float e, r;
    asm("ex2.approx.f32 %0, %1;" : "=f"(e) : "f"(u * 2.885390081777927f));
    asm("rcp.approx.f32 %0, %1;" : "=f"(r) : "f"(e + 1.0f));
    return fmaf(-2.0f, r, 1.0f);
}

// pack two f32 -> f16x2, lo in low half
__device__ __forceinline__ uint32_t pack2(float lo, float hi) {
    uint32_t r;
    asm("cvt.rn.f16x2.f32 %0, %1, %2;" : "=r"(r) : "f"(hi), "f"(lo));
    return r;
}

__device__ __forceinline__ void mma16816(float* d, const uint32_t* a,
                                         uint32_t b0, uint32_t b1) {
    asm volatile(
        "mma.sync.aligned.m16n8k16.row.col.f32.f16.f16.f32 "
        "{%0,%1,%2,%3}, {%4,%5,%6,%7}, {%8,%9}, {%0,%1,%2,%3};"
        : "+f"(d[0]), "+f"(d[1]), "+f"(d[2]), "+f"(d[3])
        : "r"(a[0]), "r"(a[1]), "r"(a[2]), "r"(a[3]), "r"(b0), "r"(b1));
}

__global__ void __launch_bounds__(NT, 1)
fp_kernel(float* __restrict__ out, const float* __restrict__ x,
          const float* __restrict__ W, const float* __restrict__ b) {
    extern __shared__ char smem[];
    const uint32_t sW = smem_u32(smem);
    float* bs = reinterpret_cast<float*>(smem + SMEM_BOFF);

    const int tid  = threadIdx.x;
    const int lane = tid & 31;
    const int warp = tid >> 5;

    // ---- W fp32 -> fp16 into swizzled SMEM ----------------------------------
    // Row n: 512 B (256 fp16). Swizzle: 16B granule XOR'ed by (n & 7) << 4.
    // Each thread converts float2 (even k) -> half2; the pair never crosses a
    // 16B granule, so one swizzled 4B store suffices.
    {
        const float2* W2 = reinterpret_cast<const float2*>(W);
        for (int idx = tid; idx < 256 * 128; idx += NT) {
            const int n = idx >> 7;             // row (output feature)
            const float2 w = W2[idx];           // idx == n*128 + k/2
            const __half2 h = __floats2half2_rn(w.x, w.y);
            uint32_t off = (uint32_t)(n * 512 + (idx & 127) * 4);
            off ^= (uint32_t)((n & 7) << 4);
            *reinterpret_cast<__half2*>(smem + off) = h;
        }
        bs[tid] = b[tid];               // NT == 256 == FEATURES
    }
    __syncthreads();                    // only sync in the kernel

    // ---- per-thread geometry ------------------------------------------------
    const int g   = lane >> 2;          // 0..7
    const int tig = lane & 3;           // 0..3
    const size_t m0 = (size_t)blockIdx.x * 128 + warp * 16 + g;
    const float* x0 = x + m0 * 256;
    const float* x1 = x0 + 8 * 256;     // row m0+8
    float* o0 = out + m0 * 256;
    float* o1 = o0 + 8 * 256;

    // ldmatrix.x4 lane addressing for a k16 x n16 B block:
    //   mat0: lanes 0-7  -> rows n0..n0+7,  k lo  (frag b0b1, n-tile low)
    //   mat1: lanes 8-15 -> rows n0..n0+7,  k hi  (frag b2b3, n-tile low)
    //   mat2: lanes16-23 -> rows n0+8..+15, k lo  (n-tile high)
    //   mat3: lanes24-31 -> rows n0+8..+15, k hi
    const int     n_lane = (lane & 7) + ((lane >> 4) << 3);
    const uint32_t lane_k = (uint32_t)(((lane >> 3) & 1) * 16); // 16B = 8 halves
    const uint32_t xorv   = (uint32_t)((lane & 7) << 4);
    const uint32_t lbase  = sW + (uint32_t)(n_lane * 512);

    uint32_t za[64];                    // z as A-fragments: [k-tile c][reg j]
    #pragma unroll
    for (int i = 0; i < 64; ++i) za[i] = 0u;

    for (int it = 0; it < ITERS; ++it) {
        const bool last = (it == ITERS - 1);
        uint32_t zn[64];

        #pragma unroll
        for (int nc = 0; nc < 4; ++nc) {            // 4 n-chunks of 64 cols
            float d[32];                            // 8 n-tiles x 4 f32
            #pragma unroll
            for (int i = 0; i < 32; ++i) d[i] = 0.0f;

            if (it) {                               // it==0: z is 0, skip GEMM
                const uint32_t chunk_base = lbase + (uint32_t)(nc * 64 * 512);
                #pragma unroll
                for (int c = 0; c < 16; ++c) {      // k-tiles (16 wide)
                    uint32_t bf[16];
                    #pragma unroll
                    for (int ntp = 0; ntp < 4; ++ntp) {
                        const uint32_t addr = chunk_base
                            + (uint32_t)(ntp * 16 * 512)
                            + ((lane_k + (uint32_t)(c * 32)) ^ xorv);
                        asm volatile(
                            "ldmatrix.sync.aligned.m8n8.x4.shared.b16 "
                            "{%0,%1,%2,%3}, [%4];"
                            : "=r"(bf[ntp * 4 + 0]), "=r"(bf[ntp * 4 + 1]),
                              "=r"(bf[ntp * 4 + 2]), "=r"(bf[ntp * 4 + 3])
                            : "r"(addr));
                    }
                    #pragma unroll
                    for (int nt = 0; nt < 8; ++nt) {
                        const int bi = (nt >> 1) * 4 + (nt & 1) * 2;
                        mma16816(&d[nt * 4], &za[c * 4], bf[bi], bf[bi + 1]);
                    }
                }
            }

            // ---- epilogue: u = D + b + x; z_new = tanh(u) -------------------
            #pragma unroll
            for (int nt = 0; nt < 8; ++nt) {
                const int n = nc * 64 + nt * 8 + tig * 2;
                const float2 bb = *reinterpret_cast<const float2*>(bs + n);
                const float2 xa = *reinterpret_cast<const float2*>(x0 + n);
                const float2 xb = *reinterpret_cast<const float2*>(x1 + n);
                const float t0 = tanh_fast(d[nt * 4 + 0] + bb.x + xa.x);
                const float t1 = tanh_fast(d[nt * 4 + 1] + bb.y + xa.y);
                const float t2 = tanh_fast(d[nt * 4 + 2] + bb.x + xb.x);
                const float t3 = tanh_fast(d[nt * 4 + 3] + bb.y + xb.y);
                if (!last) {
                    // D n-pairs map directly onto A-fragment k-pairs:
                    // k-tile c' = nc*4 + nt/2; regs (nt&1)*2 + {0,1}
                    const int ci = (nc * 4 + (nt >> 1)) * 4 + (nt & 1) * 2;
                    zn[ci + 0] = pack2(t0, t1);     // row g
                    zn[ci + 1] = pack2(t2, t3);     // row g+8
                } else {
                    *reinterpret_cast<float2*>(o0 + n) = make_float2(t0, t1);
                    *reinterpret_cast<float2*>(o1 + n) = make_float2(t2, t3);
                }
            }
        }

        if (!last) {
            #pragma unroll
            for (int i = 0; i < 64; ++i) za[i] = zn[i];
        }
    }
}

// ----------------------------------------------------------------------------
extern "C" void kernel_launch(void* const* d_in, const int* in_sizes, int n_in,
                              void* d_out, int out_size) {
    // Identify inputs by element count: x 32768*256, W 256*256, b 256.
    const float* x = nullptr;
    const float* W = nullptr;
    const float* b = nullptr;
    for (int i = 0; i < n_in; ++i) {
        if (in_sizes[i] == 32768 * 256)     x = (const float*)d_in[i];
        else if (in_sizes[i] == 256 * 256)  W = (const float*)d_in[i];
        else if (in_sizes[i] == 256)        b = (const float*)d_in[i];
    }
    if (!x && n_in > 0) x = (const float*)d_in[0];
    if (!W && n_in > 1) W = (const float*)d_in[1];
    if (!b && n_in > 2) b = (const float*)d_in[2];

    static int smem_set = 0;
    if (!smem_set) {
        cudaFuncSetAttribute(fp_kernel,
                             cudaFuncAttributeMaxDynamicSharedMemorySize,
                             SMEM_TOTAL);
        smem_set = 1;
    }
    fp_kernel<<<NB, NT, SMEM_TOTAL>>>((float*)d_out, x, W, b);
}